// round 6
// baseline (speedup 1.0000x reference)
#include <cuda_runtime.h>
#include <math.h>

#define T_  100
#define B_  64
#define I_  256
#define H_  512
#define G4  2048            // 4*H
#define TH  1536            // 3*H
#define NCTA 128

typedef unsigned long long ull;

// ------------------------- scratch (device globals) -------------------------
__device__ float g_GX[(size_t)T_ * G4 * B_];          // x@Wih^T + biases  [t][row][b]
__device__ float g_hT[(size_t)(T_ + 1) * H_ * B_];    // h transposed      [slot][k][b]
__device__ float g_D4[(size_t)T_ * B_ * 2048];        // [t][b][{di,df,dg,f}*512]

// grid barrier state
__device__ unsigned g_cnt = 0;
__device__ volatile unsigned g_gen = 0;

// ------------------------- f32x2 helpers -----------------------------------
__device__ __forceinline__ ull dup2(float x) {
    ull r; asm("mov.b64 %0, {%1, %1};" : "=l"(r) : "f"(x)); return r;
}
__device__ __forceinline__ void fma2(ull& a, ull x, ull y) {
    asm("fma.rn.f32x2 %0, %1, %2, %0;" : "+l"(a) : "l"(x), "l"(y));
}
__device__ __forceinline__ float2 unp(ull v) {
    float2 r; asm("mov.b64 {%0, %1}, %2;" : "=f"(r.x), "=f"(r.y) : "l"(v)); return r;
}
__device__ __forceinline__ float sigf(float x) { return 1.0f / (1.0f + __expf(-x)); }

// ------------------------- init: transpose initial_h ------------------------
__global__ __launch_bounds__(256) void init_hT_kernel(const float* __restrict__ ih)
{
    int u = blockIdx.x * 256 + threadIdx.x;      // 32768 threads
    int h = u >> 6, b = u & 63;
    g_hT[(size_t)h * B_ + b] = ih[b * H_ + h];
}

// ---------------------------------------------------------------------------
// GX kernel: GX[t][row][b] = sum_k x[t][b][k]*Wih[row][k] + bih[row]+bhh[row]
// ---------------------------------------------------------------------------
__global__ __launch_bounds__(256) void gx_kernel(
    const float* __restrict__ x, const float* __restrict__ wih,
    const float* __restrict__ bih, const float* __restrict__ bhh)
{
    extern __shared__ __align__(16) char smraw[];
    float* zs = (float*)smraw;                    // [2][64][64] floats (32KB)
    ull*   ws = (ull*)(smraw + 2 * 64 * 64 * 4);  // [2][64][64] ull   (64KB)

    const int tid = threadIdx.x;
    const int rowbase = blockIdx.x * 64;
    const int t = blockIdx.y;
    const float* xt = x + (size_t)t * B_ * I_;

    const int zb_ = tid & 63, zq = tid >> 6;
    const int wr_ = tid & 63, wq = tid >> 6;

    float4 zr[4], wr[4];
    auto stage_load = [&](int c) {
        const int kc0 = c * 64;
        #pragma unroll
        for (int m = 0; m < 4; m++) {
            int kl = zq * 16 + m * 4;
            zr[m] = *(const float4*)(xt + (size_t)zb_ * I_ + kc0 + kl);
            wr[m] = *(const float4*)(wih + (size_t)(rowbase + wr_) * I_ + kc0 + kl);
        }
    };
    auto stage_store = [&](int buf) {
        float* zd = zs + buf * 4096;
        ull*   wd = ws + buf * 4096;
        #pragma unroll
        for (int m = 0; m < 4; m++) {
            int kl = zq * 16 + m * 4;
            zd[(kl + 0) * 64 + zb_] = zr[m].x;
            zd[(kl + 1) * 64 + zb_] = zr[m].y;
            zd[(kl + 2) * 64 + zb_] = zr[m].z;
            zd[(kl + 3) * 64 + zb_] = zr[m].w;
            wd[(kl + 0) * 64 + wr_] = dup2(wr[m].x);
            wd[(kl + 1) * 64 + wr_] = dup2(wr[m].y);
            wd[(kl + 2) * 64 + wr_] = dup2(wr[m].z);
            wd[(kl + 3) * 64 + wr_] = dup2(wr[m].w);
        }
    };

    const int ig = tid & 15, jg = tid >> 4;
    ull a00=0,a01=0,a10=0,a11=0,a20=0,a21=0,a30=0,a31=0;

    stage_load(0); stage_store(0); __syncthreads();
    for (int c = 0; c < 4; c++) {
        const int buf = c & 1;
        if (c + 1 < 4) stage_load(c + 1);
        const float* zbp = zs + buf * 4096;
        const ull*   wbp = ws + buf * 4096;
        #pragma unroll 8
        for (int k = 0; k < 64; k++) {
            ulonglong2 zz  = *(const ulonglong2*)&zbp[k * 64 + ig * 4];
            ulonglong2 w01 = *(const ulonglong2*)&wbp[k * 64 + jg * 4];
            ulonglong2 w23 = *(const ulonglong2*)&wbp[k * 64 + jg * 4 + 2];
            fma2(a00, w01.x, zz.x); fma2(a01, w01.x, zz.y);
            fma2(a10, w01.y, zz.x); fma2(a11, w01.y, zz.y);
            fma2(a20, w23.x, zz.x); fma2(a21, w23.x, zz.y);
            fma2(a30, w23.y, zz.x); fma2(a31, w23.y, zz.y);
        }
        __syncthreads();
        if (c + 1 < 4) { stage_store(buf ^ 1); __syncthreads(); }
    }

    int r0 = rowbase + jg * 4;
    float2 u00=unp(a00),u01=unp(a01),u10=unp(a10),u11=unp(a11);
    float2 u20=unp(a20),u21=unp(a21),u30=unp(a30),u31=unp(a31);
    // vx[bl][j]: batch-local bl (ig*4+bl), row-local j (r0+j)
    float vx[4][4] = {{u00.x,u10.x,u20.x,u30.x},{u00.y,u10.y,u20.y,u30.y},
                      {u01.x,u11.x,u21.x,u31.x},{u01.y,u11.y,u21.y,u31.y}};
    #pragma unroll
    for (int j = 0; j < 4; j++) {
        float bs = bih[r0 + j] + bhh[r0 + j];
        float4 v = make_float4(vx[0][j]+bs, vx[1][j]+bs, vx[2][j]+bs, vx[3][j]+bs);
        *(float4*)(g_GX + ((size_t)t * G4 + r0 + j) * B_ + ig * 4) = v;
    }
}

// ---------------------------------------------------------------------------
// Persistent recurrent kernel: whole T loop. 128 CTAs x 256 threads, 1 wave.
// CTA owns h in [cta*4, cta*4+4): 16 gate rows x 64 batches, full K=512.
// W slice staged into smem ONCE (f32x2-dup). One grid sync per step.
// ---------------------------------------------------------------------------
__device__ __forceinline__ void gsync()
{
    __threadfence();
    __syncthreads();
    if (threadIdx.x == 0) {
        unsigned g = g_gen;
        if (atomicAdd(&g_cnt, 1) == NCTA - 1) {
            g_cnt = 0;
            __threadfence();
            g_gen = g + 1;
        } else {
            while (g_gen == g) { }
            __threadfence();
        }
    }
    __syncthreads();
}

#define TRS(ch, b, hl) trsm[((ch) * 64 + (b)) * 5 + (hl)]

__global__ __launch_bounds__(256, 1) void recurrent_kernel(
    const float* __restrict__ ic,
    const float* __restrict__ whh,
    float* __restrict__ out_h,
    float* __restrict__ out_c)
{
    extern __shared__ __align__(16) char smraw[];
    ull*   wsm  = (ull*)smraw;                          // [512][16]  64KB
    float* zsm  = (float*)(smraw + 512 * 16 * 8);       // [2][128*64] 64KB
    float* gsm  = zsm + 2 * 8192;                       // [16][64]    4KB
    float* trsm = gsm + 16 * 64;                        // [5][64][5]  6.4KB

    const int tid   = threadIdx.x;
    const int cta   = blockIdx.x;
    const int hbase = cta * 4;

    // ---- stage W once: rows {g*512 + hbase + hl}, local r = g*4 + hl ----
    {
        const int r = tid >> 4, kq = tid & 15;
        const int row = (r >> 2) * H_ + hbase + (r & 3);
        const float* wrow = whh + (size_t)row * H_;
        #pragma unroll
        for (int i = 0; i < 32; i += 4) {
            float4 v = *(const float4*)(wrow + kq * 32 + i);
            wsm[(kq * 32 + i + 0) * 16 + r] = dup2(v.x);
            wsm[(kq * 32 + i + 1) * 16 + r] = dup2(v.y);
            wsm[(kq * 32 + i + 2) * 16 + r] = dup2(v.z);
            wsm[(kq * 32 + i + 3) * 16 + r] = dup2(v.w);
        }
    }

    // ---- per-thread state ----
    const int r  = tid >> 4;      // GEMM: local row
    const int bg = tid & 15;      // GEMM: batch group (4 batches)
    const int hl = tid >> 6;      // ew:   h-local (0..3)
    const int b  = tid & 63;      // ew:   batch
    float creg = ic[(size_t)b * H_ + hbase + hl];

    __syncthreads();

    float4 zr[8];
    for (int t = 0; t < T_; t++) {
        if (t > 0) gsync();       // hT(t) ready (t=0: written by init kernel)

        const float4* hTt = (const float4*)(g_hT + (size_t)t * H_ * B_);

        auto zload = [&](int c) {
            const float4* src = hTt + c * 2048;
            #pragma unroll
            for (int m = 0; m < 8; m++) zr[m] = __ldcg(src + m * 256 + tid);
        };
        auto zstore = [&](int buf) {
            float4* d = (float4*)(zsm + buf * 8192);
            #pragma unroll
            for (int m = 0; m < 8; m++) d[m * 256 + tid] = zr[m];
        };

        ull a0 = 0, a1 = 0;       // 1 row x 4 batches

        zload(0); zstore(0); __syncthreads();
        for (int c = 0; c < 4; c++) {
            const int buf = c & 1;
            if (c + 1 < 4) zload(c + 1);
            const ull*   wp = wsm + (c * 128) * 16 + r;
            const float* zp = zsm + buf * 8192 + bg * 4;
            #pragma unroll 16
            for (int kl = 0; kl < 128; kl++) {
                ull w = wp[kl * 16];
                ulonglong2 z = *(const ulonglong2*)(zp + kl * 64);
                fma2(a0, w, z.x);
                fma2(a1, w, z.y);
            }
            __syncthreads();
            if (c + 1 < 4) { zstore(buf ^ 1); __syncthreads(); }
        }

        // gate exchange
        {
            float2 u0 = unp(a0), u1 = unp(a1);
            gsm[r * 64 + bg * 4 + 0] = u0.x;
            gsm[r * 64 + bg * 4 + 1] = u0.y;
            gsm[r * 64 + bg * 4 + 2] = u1.x;
            gsm[r * 64 + bg * 4 + 3] = u1.y;
        }
        __syncthreads();

        // elementwise update for (hbase+hl, b)
        {
            const size_t gxb = ((size_t)t * G4 + hbase + hl) * B_ + b;
            float gi = gsm[(0  + hl) * 64 + b] + g_GX[gxb];
            float gf = gsm[(4  + hl) * 64 + b] + g_GX[gxb + (size_t)H_ * B_];
            float gg = gsm[(8  + hl) * 64 + b] + g_GX[gxb + (size_t)2 * H_ * B_];
            float go = gsm[(12 + hl) * 64 + b] + g_GX[gxb + (size_t)3 * H_ * B_];

            float i_ = sigf(gi);
            float f_ = sigf(gf);
            float g_ = tanhf(gg);
            float o_ = sigf(go);

            float cy = f_ * creg + i_ * g_;
            float hy = o_ * tanhf(cy);

            TRS(0, b, hl) = g_ * i_ * (1.f - i_);
            TRS(1, b, hl) = creg * f_ * (1.f - f_);
            TRS(2, b, hl) = i_ * (1.f - g_ * g_);
            TRS(3, b, hl) = f_;
            TRS(4, b, hl) = hy;
            creg = cy;

            __stcg(g_hT + ((size_t)(t + 1) * H_ + hbase + hl) * B_ + b, hy);
        }
        __syncthreads();

        // coalesced float4 writes of the transposed per-CTA outputs
        for (int task = tid; task < 320; task += 256) {
            int ch = task >> 6, bb = task & 63;
            float4 v = make_float4(TRS(ch, bb, 0), TRS(ch, bb, 1),
                                   TRS(ch, bb, 2), TRS(ch, bb, 3));
            if (ch < 4)
                *(float4*)(g_D4 + ((size_t)t * B_ + bb) * 2048 + ch * H_ + hbase) = v;
            else
                *(float4*)(out_h + ((size_t)t * B_ + bb) * H_ + hbase) = v;
        }
        __syncthreads();
    }

    out_c[(size_t)b * H_ + hbase + hl] = creg;
}

// ---------------------------------------------------------------------------
// scan: suffix product of f scales d channels in place; accumulates ev_b.
// ---------------------------------------------------------------------------
__global__ __launch_bounds__(256) void scan_kernel(float* __restrict__ out_evb)
{
    const int u = blockIdx.x * 256 + threadIdx.x;
    const int b = u >> 9, h = u & (H_ - 1);
    float coef = 1.f, si = 0.f, sf = 0.f, sg = 0.f;
    for (int t = T_ - 1; t >= 0; t--) {
        size_t base = ((size_t)t * B_ + b) * 2048;
        float f  = g_D4[base + 3 * H_ + h];
        float di = g_D4[base + h]          * coef;
        float df = g_D4[base + H_ + h]     * coef;
        float dg = g_D4[base + 2 * H_ + h] * coef;
        g_D4[base + h]          = di;
        g_D4[base + H_ + h]     = df;
        g_D4[base + 2 * H_ + h] = dg;
        si += di; sf += df; sg += dg;
        coef *= f;
    }
    out_evb[b * TH + h]          = si;
    out_evb[b * TH + H_ + h]     = sf;
    out_evb[b * TH + 2 * H_ + h] = sg;
}

// ---------------------------------------------------------------------------
// phase 3: C[b] = D_b^T (3H x T) @ Z_b (T x N), f32x2.
// ---------------------------------------------------------------------------
__global__ __launch_bounds__(256) void outer_kernel(
    const float* __restrict__ src, const float* __restrict__ init_h,
    const float* __restrict__ out_h, float* __restrict__ outC, int N, int mode)
{
    extern __shared__ __align__(16) char smraw[];
    ull*   Dsm = (ull*)smraw;                            // [T_][64] dup'd
    float* Xsm = (float*)(smraw + (size_t)T_ * 64 * 8);  // [T_][64]

    const int tid = threadIdx.x;
    const int ibase = blockIdx.x * 64, jbase = blockIdx.y * 64, b = blockIdx.z;

    for (int idx = tid; idx < T_ * 16; idx += 256) {
        int t = idx >> 4, j4 = (idx & 15) * 4;
        float4 v = *(const float4*)(g_D4 + ((size_t)t * B_ + b) * 2048 + jbase + j4);
        Dsm[t * 64 + j4 + 0] = dup2(v.x);
        Dsm[t * 64 + j4 + 1] = dup2(v.y);
        Dsm[t * 64 + j4 + 2] = dup2(v.z);
        Dsm[t * 64 + j4 + 3] = dup2(v.w);
    }
    for (int idx = tid; idx < T_ * 16; idx += 256) {
        int t = idx >> 4, i4 = (idx & 15) * 4;
        const float* p;
        if (mode == 0) p = src + ((size_t)t * B_ + b) * I_ + ibase + i4;
        else p = (t == 0) ? (init_h + (size_t)b * H_ + ibase + i4)
                          : (out_h + ((size_t)(t - 1) * B_ + b) * H_ + ibase + i4);
        *(float4*)&Xsm[t * 64 + i4] = *(const float4*)p;
    }
    __syncthreads();

    const int jg = tid >> 4, ig = tid & 15;
    ull a00=0,a01=0,a10=0,a11=0,a20=0,a21=0,a30=0,a31=0;

    #pragma unroll 4
    for (int t = 0; t < T_; t++) {
        ulonglong2 d01 = *(const ulonglong2*)&Dsm[t * 64 + jg * 4];
        ulonglong2 d23 = *(const ulonglong2*)&Dsm[t * 64 + jg * 4 + 2];
        ulonglong2 xx  = *(const ulonglong2*)&Xsm[t * 64 + ig * 4];
        fma2(a00, d01.x, xx.x); fma2(a01, d01.x, xx.y);
        fma2(a10, d01.y, xx.x); fma2(a11, d01.y, xx.y);
        fma2(a20, d23.x, xx.x); fma2(a21, d23.x, xx.y);
        fma2(a30, d23.y, xx.x); fma2(a31, d23.y, xx.y);
    }

    size_t obase = (size_t)b * TH * N + ibase + ig * 4;
    const int j0 = jbase + jg * 4;
    float2 u; float4 v;
    u = unp(a00); v.x = u.x; v.y = u.y; u = unp(a01); v.z = u.x; v.w = u.y;
    *(float4*)(outC + obase + (size_t)(j0 + 0) * N) = v;
    u = unp(a10); v.x = u.x; v.y = u.y; u = unp(a11); v.z = u.x; v.w = u.y;
    *(float4*)(outC + obase + (size_t)(j0 + 1) * N) = v;
    u = unp(a20); v.x = u.x; v.y = u.y; u = unp(a21); v.z = u.x; v.w = u.y;
    *(float4*)(outC + obase + (size_t)(j0 + 2) * N) = v;
    u = unp(a30); v.x = u.x; v.y = u.y; u = unp(a31); v.z = u.x; v.w = u.y;
    *(float4*)(outC + obase + (size_t)(j0 + 3) * N) = v;
}

// ---------------------------------------------------------------------------

extern "C" void kernel_launch(void* const* d_in, const int* in_sizes, int n_in,
                              void* d_out, int out_size)
{
    const float* input = (const float*)d_in[0];
    const float* ih    = (const float*)d_in[1];
    const float* ic    = (const float*)d_in[2];
    const float* wih   = (const float*)d_in[3];
    const float* whh   = (const float*)d_in[4];
    const float* bih   = (const float*)d_in[5];
    const float* bhh   = (const float*)d_in[6];

    float* out      = (float*)d_out;
    float* out_h    = out;                                // [T,B,H]
    float* out_c    = out_h  + (size_t)T_ * B_ * H_;      // [B,H]
    float* out_evih = out_c  + (size_t)B_ * H_;           // [B,3H,I]
    float* out_evhh = out_evih + (size_t)B_ * TH * I_;    // [B,3H,H]
    float* out_evb  = out_evhh + (size_t)B_ * TH * H_;    // [B,3H,1]

    const int smem_gemm  = 2 * 64 * 64 * 4 + 2 * 64 * 64 * 8;              // 96KB
    const int smem_rec   = 512 * 16 * 8 + 2 * 8192 * 4 + 16 * 64 * 4
                         + 5 * 64 * 5 * 4;                                  // ~139KB
    const int smem_outer = T_ * 64 * 8 + T_ * 64 * 4;                       // 75KB

    cudaFuncSetAttribute(gx_kernel, cudaFuncAttributeMaxDynamicSharedMemorySize, smem_gemm);
    cudaFuncSetAttribute(recurrent_kernel, cudaFuncAttributeMaxDynamicSharedMemorySize, smem_rec);
    cudaFuncSetAttribute(outer_kernel, cudaFuncAttributeMaxDynamicSharedMemorySize, smem_outer);

    init_hT_kernel<<<128, 256>>>(ih);
    gx_kernel<<<dim3(32, T_), 256, smem_gemm>>>(input, wih, bih, bhh);

    recurrent_kernel<<<NCTA, 256, smem_rec>>>(ic, whh, out_h, out_c);

    scan_kernel<<<128, 256>>>(out_evb);

    outer_kernel<<<dim3(I_ / 64, TH / 64, B_), 256, smem_outer>>>(
        input, ih, out_h, out_evih, I_, 0);
    outer_kernel<<<dim3(H_ / 64, TH / 64, B_), 256, smem_outer>>>(
        input, ih, out_h, out_evhh, H_, 1);
}

// round 7
// speedup vs baseline: 1.3065x; 1.3065x over previous
#include <cuda_runtime.h>
#include <math.h>

#define T_  100
#define B_  64
#define I_  256
#define H_  512
#define G4  2048            // 4*H
#define TH  1536            // 3*H
#define NCTA 128

typedef unsigned long long ull;

// ------------------------- scratch (device globals) -------------------------
__device__ float g_GX[(size_t)T_ * G4 * B_];          // x@Wih^T + biases  [t][row][b]
__device__ float g_hT[(size_t)(T_ + 1) * H_ * B_];    // h transposed      [slot][k][b]
__device__ float g_D4[(size_t)T_ * B_ * 2048];        // [t][b][{di,df,dg,f}*512]

// grid barrier state
__device__ unsigned g_cnt = 0;
__device__ volatile unsigned g_gen = 0;

// ------------------------- f32x2 helpers -----------------------------------
__device__ __forceinline__ ull dup2(float x) {
    ull r; asm("mov.b64 %0, {%1, %1};" : "=l"(r) : "f"(x)); return r;
}
__device__ __forceinline__ void fma2(ull& a, ull x, ull y) {
    asm("fma.rn.f32x2 %0, %1, %2, %0;" : "+l"(a) : "l"(x), "l"(y));
}
__device__ __forceinline__ float2 unp(ull v) {
    float2 r; asm("mov.b64 {%0, %1}, %2;" : "=f"(r.x), "=f"(r.y) : "l"(v)); return r;
}
__device__ __forceinline__ float sigf(float x) { return 1.0f / (1.0f + __expf(-x)); }

// ------------------------- init: transpose initial_h ------------------------
__global__ __launch_bounds__(256) void init_hT_kernel(const float* __restrict__ ih)
{
    int u = blockIdx.x * 256 + threadIdx.x;      // 32768 threads
    int h = u >> 6, b = u & 63;
    g_hT[(size_t)h * B_ + b] = ih[b * H_ + h];
}

// ---------------------------------------------------------------------------
// GX kernel: GX[t][row][b] = sum_k x[t][b][k]*Wih[row][k] + bih[row]+bhh[row]
// ---------------------------------------------------------------------------
__global__ __launch_bounds__(256) void gx_kernel(
    const float* __restrict__ x, const float* __restrict__ wih,
    const float* __restrict__ bih, const float* __restrict__ bhh)
{
    extern __shared__ __align__(16) char smraw[];
    float* zs = (float*)smraw;                    // [2][64][64] floats (32KB)
    ull*   ws = (ull*)(smraw + 2 * 64 * 64 * 4);  // [2][64][64] ull   (64KB)

    const int tid = threadIdx.x;
    const int rowbase = blockIdx.x * 64;
    const int t = blockIdx.y;
    const float* xt = x + (size_t)t * B_ * I_;

    const int zb_ = tid & 63, zq = tid >> 6;
    const int wr_ = tid & 63, wq = tid >> 6;

    float4 zr[4], wr[4];
    auto stage_load = [&](int c) {
        const int kc0 = c * 64;
        #pragma unroll
        for (int m = 0; m < 4; m++) {
            int kl = zq * 16 + m * 4;
            zr[m] = *(const float4*)(xt + (size_t)zb_ * I_ + kc0 + kl);
            wr[m] = *(const float4*)(wih + (size_t)(rowbase + wr_) * I_ + kc0 + kl);
        }
    };
    auto stage_store = [&](int buf) {
        float* zd = zs + buf * 4096;
        ull*   wd = ws + buf * 4096;
        #pragma unroll
        for (int m = 0; m < 4; m++) {
            int kl = zq * 16 + m * 4;
            zd[(kl + 0) * 64 + zb_] = zr[m].x;
            zd[(kl + 1) * 64 + zb_] = zr[m].y;
            zd[(kl + 2) * 64 + zb_] = zr[m].z;
            zd[(kl + 3) * 64 + zb_] = zr[m].w;
            wd[(kl + 0) * 64 + wr_] = dup2(wr[m].x);
            wd[(kl + 1) * 64 + wr_] = dup2(wr[m].y);
            wd[(kl + 2) * 64 + wr_] = dup2(wr[m].z);
            wd[(kl + 3) * 64 + wr_] = dup2(wr[m].w);
        }
    };

    const int ig = tid & 15, jg = tid >> 4;
    ull a00=0,a01=0,a10=0,a11=0,a20=0,a21=0,a30=0,a31=0;

    stage_load(0); stage_store(0); __syncthreads();
    for (int c = 0; c < 4; c++) {
        const int buf = c & 1;
        if (c + 1 < 4) stage_load(c + 1);
        const float* zbp = zs + buf * 4096;
        const ull*   wbp = ws + buf * 4096;
        #pragma unroll 8
        for (int k = 0; k < 64; k++) {
            ulonglong2 zz  = *(const ulonglong2*)&zbp[k * 64 + ig * 4];
            ulonglong2 w01 = *(const ulonglong2*)&wbp[k * 64 + jg * 4];
            ulonglong2 w23 = *(const ulonglong2*)&wbp[k * 64 + jg * 4 + 2];
            fma2(a00, w01.x, zz.x); fma2(a01, w01.x, zz.y);
            fma2(a10, w01.y, zz.x); fma2(a11, w01.y, zz.y);
            fma2(a20, w23.x, zz.x); fma2(a21, w23.x, zz.y);
            fma2(a30, w23.y, zz.x); fma2(a31, w23.y, zz.y);
        }
        __syncthreads();
        if (c + 1 < 4) { stage_store(buf ^ 1); __syncthreads(); }
    }

    int r0 = rowbase + jg * 4;
    float2 u00=unp(a00),u01=unp(a01),u10=unp(a10),u11=unp(a11);
    float2 u20=unp(a20),u21=unp(a21),u30=unp(a30),u31=unp(a31);
    float vx[4][4] = {{u00.x,u10.x,u20.x,u30.x},{u00.y,u10.y,u20.y,u30.y},
                      {u01.x,u11.x,u21.x,u31.x},{u01.y,u11.y,u21.y,u31.y}};
    #pragma unroll
    for (int j = 0; j < 4; j++) {
        float bs = bih[r0 + j] + bhh[r0 + j];
        float4 v = make_float4(vx[0][j]+bs, vx[1][j]+bs, vx[2][j]+bs, vx[3][j]+bs);
        *(float4*)(g_GX + ((size_t)t * G4 + r0 + j) * B_ + ig * 4) = v;
    }
}

// ---------------------------------------------------------------------------
// grid barrier
// ---------------------------------------------------------------------------
__device__ __forceinline__ void gsync()
{
    __threadfence();
    __syncthreads();
    if (threadIdx.x == 0) {
        unsigned g = g_gen;
        if (atomicAdd(&g_cnt, 1) == NCTA - 1) {
            g_cnt = 0;
            __threadfence();
            g_gen = g + 1;
        } else {
            while (g_gen == g) { }
            __threadfence();
        }
    }
    __syncthreads();
}

// ---------------------------------------------------------------------------
// Persistent recurrent kernel. 128 CTAs x 256 threads, 1 wave, 1 sync/step.
// CTA owns 4 h-values: 16 gate rows x 64 batches, full K=512 via internal
// 4-way K-split. Thread = (ks, jg, ig): 4 rows (gate jg) x 4 batches, 128 k.
// W slice (16 rows x 512 k, f32x2-dup, 64KB) resident in smem for all steps.
// z (hT step slice, 131KB) staged each step; partial/transpose buffers
// overlay the z region after compute.
// ---------------------------------------------------------------------------
#define TRS(ch, b, hl) trsm[((ch) * 64 + (b)) * 5 + (hl)]

__global__ __launch_bounds__(256, 1) void recurrent_kernel(
    const float* __restrict__ ic,
    const float* __restrict__ whh,
    float* __restrict__ out_h,
    float* __restrict__ out_c)
{
    extern __shared__ __align__(16) char smraw[];
    ull*   wsm  = (ull*)smraw;                    // [512][16]   64KB, resident
    float* zsm  = (float*)(smraw + 512 * 16 * 8); // [512][64]  131KB, per step
    float* psm  = zsm;                            // overlay: [4ks][16r][64b] 16KB
    float* trsm = zsm + 4096;                     // overlay: [5][64][5] 6.4KB

    const int tid   = threadIdx.x;
    const int cta   = blockIdx.x;
    const int hbase = cta * 4;

    // ---- stage W once: local row r = g*4+hl -> global row g*512+hbase+hl ----
    {
        const int r = tid >> 4, kq = tid & 15;
        const int row = (r >> 2) * H_ + hbase + (r & 3);
        const float* wrow = whh + (size_t)row * H_;
        #pragma unroll
        for (int i = 0; i < 32; i += 4) {
            float4 v = *(const float4*)(wrow + kq * 32 + i);
            wsm[(kq * 32 + i + 0) * 16 + r] = dup2(v.x);
            wsm[(kq * 32 + i + 1) * 16 + r] = dup2(v.y);
            wsm[(kq * 32 + i + 2) * 16 + r] = dup2(v.z);
            wsm[(kq * 32 + i + 3) * 16 + r] = dup2(v.w);
        }
    }

    // ---- per-thread maps ----
    const int ks = tid >> 6;            // k-slice (0..3)
    const int jg = (tid >> 4) & 3;      // gate / row-group (4 rows)
    const int ig = tid & 15;            // batch group (4 batches)
    const int hl = tid >> 6;            // ew: h-local (0..3)
    const int b  = tid & 63;            // ew: batch
    float creg = ic[(size_t)b * H_ + hbase + hl];

    __syncthreads();

    for (int t = 0; t < T_; t++) {
        if (t > 0) gsync();             // hT(t) visible chip-wide

        // ---- stage z = hT[t] (131KB), straight coalesced copy ----
        {
            const float4* src = (const float4*)(g_hT + (size_t)t * H_ * B_);
            float4* dst = (float4*)zsm;
            #pragma unroll 8
            for (int m = 0; m < 32; m++)
                dst[m * 256 + tid] = __ldcg(src + m * 256 + tid);
        }
        __syncthreads();

        // ---- GEMM: 4 rows x 4 batches, k in [ks*128, ks*128+128) ----
        ull a00=0,a01=0,a10=0,a11=0,a20=0,a21=0,a30=0,a31=0;
        {
            const ull*   wp = wsm + (size_t)ks * 128 * 16 + jg * 4;
            const float* zp = zsm + (size_t)ks * 128 * 64 + ig * 4;
            #pragma unroll 8
            for (int kl = 0; kl < 128; kl++) {
                ulonglong2 w01 = *(const ulonglong2*)(wp + kl * 16);
                ulonglong2 w23 = *(const ulonglong2*)(wp + kl * 16 + 2);
                ulonglong2 zz  = *(const ulonglong2*)(zp + kl * 64);
                fma2(a00, w01.x, zz.x); fma2(a01, w01.x, zz.y);
                fma2(a10, w01.y, zz.x); fma2(a11, w01.y, zz.y);
                fma2(a20, w23.x, zz.x); fma2(a21, w23.x, zz.y);
                fma2(a30, w23.y, zz.x); fma2(a31, w23.y, zz.y);
            }
        }
        __syncthreads();   // everyone done reading zsm -> safe to overlay psm

        // ---- write partials: psm[ks][jg*4 + r][64b] ----
        {
            float2 u0, u1;
            u0 = unp(a00); u1 = unp(a01);
            *(float4*)&psm[((ks * 16) + jg * 4 + 0) * 64 + ig * 4] = make_float4(u0.x,u0.y,u1.x,u1.y);
            u0 = unp(a10); u1 = unp(a11);
            *(float4*)&psm[((ks * 16) + jg * 4 + 1) * 64 + ig * 4] = make_float4(u0.x,u0.y,u1.x,u1.y);
            u0 = unp(a20); u1 = unp(a21);
            *(float4*)&psm[((ks * 16) + jg * 4 + 2) * 64 + ig * 4] = make_float4(u0.x,u0.y,u1.x,u1.y);
            u0 = unp(a30); u1 = unp(a31);
            *(float4*)&psm[((ks * 16) + jg * 4 + 3) * 64 + ig * 4] = make_float4(u0.x,u0.y,u1.x,u1.y);
        }
        __syncthreads();

        // ---- fused elementwise for (hbase+hl, b) ----
        {
            const size_t gxb = ((size_t)t * G4 + hbase + hl) * B_ + b;
            float gi = g_GX[gxb];
            float gf = g_GX[gxb + (size_t)H_ * B_];
            float gg = g_GX[gxb + (size_t)2 * H_ * B_];
            float go = g_GX[gxb + (size_t)3 * H_ * B_];
            #pragma unroll
            for (int s = 0; s < 4; s++) {
                gi += psm[(s * 16 + 0 * 4 + hl) * 64 + b];
                gf += psm[(s * 16 + 1 * 4 + hl) * 64 + b];
                gg += psm[(s * 16 + 2 * 4 + hl) * 64 + b];
                go += psm[(s * 16 + 3 * 4 + hl) * 64 + b];
            }

            float i_ = sigf(gi);
            float f_ = sigf(gf);
            float g_ = tanhf(gg);
            float o_ = sigf(go);

            float cy = f_ * creg + i_ * g_;
            float hy = o_ * tanhf(cy);

            TRS(0, b, hl) = g_ * i_ * (1.f - i_);
            TRS(1, b, hl) = creg * f_ * (1.f - f_);
            TRS(2, b, hl) = i_ * (1.f - g_ * g_);
            TRS(3, b, hl) = f_;
            TRS(4, b, hl) = hy;
            creg = cy;

            __stcg(g_hT + ((size_t)(t + 1) * H_ + hbase + hl) * B_ + b, hy);
        }
        __syncthreads();

        // ---- coalesced float4 writes of transposed per-CTA outputs ----
        for (int task = tid; task < 320; task += 256) {
            int ch = task >> 6, bb = task & 63;
            float4 v = make_float4(TRS(ch, bb, 0), TRS(ch, bb, 1),
                                   TRS(ch, bb, 2), TRS(ch, bb, 3));
            if (ch < 4)
                *(float4*)(g_D4 + ((size_t)t * B_ + bb) * 2048 + ch * H_ + hbase) = v;
            else
                *(float4*)(out_h + ((size_t)t * B_ + bb) * H_ + hbase) = v;
        }
        __syncthreads();
    }

    out_c[(size_t)b * H_ + hbase + hl] = creg;
}

// ---------------------------------------------------------------------------
// scan: suffix product of f scales d channels in place; accumulates ev_b.
// ---------------------------------------------------------------------------
__global__ __launch_bounds__(256) void scan_kernel(float* __restrict__ out_evb)
{
    const int u = blockIdx.x * 256 + threadIdx.x;
    const int b = u >> 9, h = u & (H_ - 1);
    float coef = 1.f, si = 0.f, sf = 0.f, sg = 0.f;
    for (int t = T_ - 1; t >= 0; t--) {
        size_t base = ((size_t)t * B_ + b) * 2048;
        float f  = g_D4[base + 3 * H_ + h];
        float di = g_D4[base + h]          * coef;
        float df = g_D4[base + H_ + h]     * coef;
        float dg = g_D4[base + 2 * H_ + h] * coef;
        g_D4[base + h]          = di;
        g_D4[base + H_ + h]     = df;
        g_D4[base + 2 * H_ + h] = dg;
        si += di; sf += df; sg += dg;
        coef *= f;
    }
    out_evb[b * TH + h]          = si;
    out_evb[b * TH + H_ + h]     = sf;
    out_evb[b * TH + 2 * H_ + h] = sg;
}

// ---------------------------------------------------------------------------
// phase 3: C[b] = D_b^T (3H x T) @ Z_b (T x N), f32x2.
// ---------------------------------------------------------------------------
__global__ __launch_bounds__(256) void outer_kernel(
    const float* __restrict__ src, const float* __restrict__ init_h,
    const float* __restrict__ out_h, float* __restrict__ outC, int N, int mode)
{
    extern __shared__ __align__(16) char smraw[];
    ull*   Dsm = (ull*)smraw;                            // [T_][64] dup'd
    float* Xsm = (float*)(smraw + (size_t)T_ * 64 * 8);  // [T_][64]

    const int tid = threadIdx.x;
    const int ibase = blockIdx.x * 64, jbase = blockIdx.y * 64, b = blockIdx.z;

    for (int idx = tid; idx < T_ * 16; idx += 256) {
        int t = idx >> 4, j4 = (idx & 15) * 4;
        float4 v = *(const float4*)(g_D4 + ((size_t)t * B_ + b) * 2048 + jbase + j4);
        Dsm[t * 64 + j4 + 0] = dup2(v.x);
        Dsm[t * 64 + j4 + 1] = dup2(v.y);
        Dsm[t * 64 + j4 + 2] = dup2(v.z);
        Dsm[t * 64 + j4 + 3] = dup2(v.w);
    }
    for (int idx = tid; idx < T_ * 16; idx += 256) {
        int t = idx >> 4, i4 = (idx & 15) * 4;
        const float* p;
        if (mode == 0) p = src + ((size_t)t * B_ + b) * I_ + ibase + i4;
        else p = (t == 0) ? (init_h + (size_t)b * H_ + ibase + i4)
                          : (out_h + ((size_t)(t - 1) * B_ + b) * H_ + ibase + i4);
        *(float4*)&Xsm[t * 64 + i4] = *(const float4*)p;
    }
    __syncthreads();

    const int jg = tid >> 4, ig = tid & 15;
    ull a00=0,a01=0,a10=0,a11=0,a20=0,a21=0,a30=0,a31=0;

    #pragma unroll 4
    for (int t = 0; t < T_; t++) {
        ulonglong2 d01 = *(const ulonglong2*)&Dsm[t * 64 + jg * 4];
        ulonglong2 d23 = *(const ulonglong2*)&Dsm[t * 64 + jg * 4 + 2];
        ulonglong2 xx  = *(const ulonglong2*)&Xsm[t * 64 + ig * 4];
        fma2(a00, d01.x, xx.x); fma2(a01, d01.x, xx.y);
        fma2(a10, d01.y, xx.x); fma2(a11, d01.y, xx.y);
        fma2(a20, d23.x, xx.x); fma2(a21, d23.x, xx.y);
        fma2(a30, d23.y, xx.x); fma2(a31, d23.y, xx.y);
    }

    size_t obase = (size_t)b * TH * N + ibase + ig * 4;
    const int j0 = jbase + jg * 4;
    float2 u; float4 v;
    u = unp(a00); v.x = u.x; v.y = u.y; u = unp(a01); v.z = u.x; v.w = u.y;
    *(float4*)(outC + obase + (size_t)(j0 + 0) * N) = v;
    u = unp(a10); v.x = u.x; v.y = u.y; u = unp(a11); v.z = u.x; v.w = u.y;
    *(float4*)(outC + obase + (size_t)(j0 + 1) * N) = v;
    u = unp(a20); v.x = u.x; v.y = u.y; u = unp(a21); v.z = u.x; v.w = u.y;
    *(float4*)(outC + obase + (size_t)(j0 + 2) * N) = v;
    u = unp(a30); v.x = u.x; v.y = u.y; u = unp(a31); v.z = u.x; v.w = u.y;
    *(float4*)(outC + obase + (size_t)(j0 + 3) * N) = v;
}

// ---------------------------------------------------------------------------

extern "C" void kernel_launch(void* const* d_in, const int* in_sizes, int n_in,
                              void* d_out, int out_size)
{
    const float* input = (const float*)d_in[0];
    const float* ih    = (const float*)d_in[1];
    const float* ic    = (const float*)d_in[2];
    const float* wih   = (const float*)d_in[3];
    const float* whh   = (const float*)d_in[4];
    const float* bih   = (const float*)d_in[5];
    const float* bhh   = (const float*)d_in[6];

    float* out      = (float*)d_out;
    float* out_h    = out;                                // [T,B,H]
    float* out_c    = out_h  + (size_t)T_ * B_ * H_;      // [B,H]
    float* out_evih = out_c  + (size_t)B_ * H_;           // [B,3H,I]
    float* out_evhh = out_evih + (size_t)B_ * TH * I_;    // [B,3H,H]
    float* out_evb  = out_evhh + (size_t)B_ * TH * H_;    // [B,3H,1]

    const int smem_gemm  = 2 * 64 * 64 * 4 + 2 * 64 * 64 * 8;   // 96KB
    const int smem_rec   = 512 * 16 * 8 + 512 * 64 * 4;         // 192KB
    const int smem_outer = T_ * 64 * 8 + T_ * 64 * 4;           // 75KB

    cudaFuncSetAttribute(gx_kernel, cudaFuncAttributeMaxDynamicSharedMemorySize, smem_gemm);
    cudaFuncSetAttribute(recurrent_kernel, cudaFuncAttributeMaxDynamicSharedMemorySize, smem_rec);
    cudaFuncSetAttribute(outer_kernel, cudaFuncAttributeMaxDynamicSharedMemorySize, smem_outer);

    init_hT_kernel<<<128, 256>>>(ih);
    gx_kernel<<<dim3(32, T_), 256, smem_gemm>>>(input, wih, bih, bhh);

    recurrent_kernel<<<NCTA, 256, smem_rec>>>(ic, whh, out_h, out_c);

    scan_kernel<<<128, 256>>>(out_evb);

    outer_kernel<<<dim3(I_ / 64, TH / 64, B_), 256, smem_outer>>>(
        input, ih, out_h, out_evih, I_, 0);
    outer_kernel<<<dim3(H_ / 64, TH / 64, B_), 256, smem_outer>>>(
        input, ih, out_h, out_evhh, H_, 1);
}

// round 8
// speedup vs baseline: 1.3353x; 1.0220x over previous
#include <cuda_runtime.h>
#include <math.h>

#define T_  100
#define B_  64
#define I_  256
#define H_  512
#define G4  2048            // 4*H
#define TH  1536            // 3*H
#define HT  8               // h per CTA
#define BT  32              // batches per CTA
#define NGRP 64             // CTAs per barrier group

typedef unsigned long long ull;

// ------------------------- scratch (device globals) -------------------------
__device__ float g_GX[(size_t)T_ * G4 * B_];          // x@Wih^T + biases  [t][row][b]
__device__ float g_hT[(size_t)(T_ + 1) * H_ * B_];    // h transposed      [slot][k][b]
__device__ float g_D4[(size_t)T_ * B_ * 2048];        // [t][b][{di,df,dg,f}*512]

// grid barrier state (one per btile group)
__device__ unsigned g_cnt2[2] = {0, 0};
__device__ volatile unsigned g_gen2[2] = {0, 0};

// ------------------------- f32x2 helpers -----------------------------------
__device__ __forceinline__ ull dup2(float x) {
    ull r; asm("mov.b64 %0, {%1, %1};" : "=l"(r) : "f"(x)); return r;
}
__device__ __forceinline__ void fma2(ull& a, ull x, ull y) {
    asm("fma.rn.f32x2 %0, %1, %2, %0;" : "+l"(a) : "l"(x), "l"(y));
}
__device__ __forceinline__ float2 unp(ull v) {
    float2 r; asm("mov.b64 {%0, %1}, %2;" : "=f"(r.x), "=f"(r.y) : "l"(v)); return r;
}
__device__ __forceinline__ float sigf(float x) { return 1.0f / (1.0f + __expf(-x)); }
__device__ __forceinline__ float tanhfast(float x) {
    float e = __expf(-2.0f * fabsf(x));
    float r = (1.0f - e) / (1.0f + e);
    return copysignf(r, x);
}

// ------------------------- init: transpose initial_h ------------------------
__global__ __launch_bounds__(256) void init_hT_kernel(const float* __restrict__ ih)
{
    int u = blockIdx.x * 256 + threadIdx.x;      // 32768 threads
    int h = u >> 6, b = u & 63;
    g_hT[(size_t)h * B_ + b] = ih[b * H_ + h];
}

// ---------------------------------------------------------------------------
// GX kernel: GX[t][row][b] = sum_k x[t][b][k]*Wih[row][k] + bih[row]+bhh[row]
// ---------------------------------------------------------------------------
__global__ __launch_bounds__(256) void gx_kernel(
    const float* __restrict__ x, const float* __restrict__ wih,
    const float* __restrict__ bih, const float* __restrict__ bhh)
{
    extern __shared__ __align__(16) char smraw[];
    float* zs = (float*)smraw;                    // [2][64][64] floats (32KB)
    ull*   ws = (ull*)(smraw + 2 * 64 * 64 * 4);  // [2][64][64] ull   (64KB)

    const int tid = threadIdx.x;
    const int rowbase = blockIdx.x * 64;
    const int t = blockIdx.y;
    const float* xt = x + (size_t)t * B_ * I_;

    const int zb_ = tid & 63, zq = tid >> 6;
    const int wr_ = tid & 63, wq = tid >> 6;

    float4 zr[4], wr[4];
    auto stage_load = [&](int c) {
        const int kc0 = c * 64;
        #pragma unroll
        for (int m = 0; m < 4; m++) {
            int kl = zq * 16 + m * 4;
            zr[m] = *(const float4*)(xt + (size_t)zb_ * I_ + kc0 + kl);
            wr[m] = *(const float4*)(wih + (size_t)(rowbase + wr_) * I_ + kc0 + kl);
        }
    };
    auto stage_store = [&](int buf) {
        float* zd = zs + buf * 4096;
        ull*   wd = ws + buf * 4096;
        #pragma unroll
        for (int m = 0; m < 4; m++) {
            int kl = zq * 16 + m * 4;
            zd[(kl + 0) * 64 + zb_] = zr[m].x;
            zd[(kl + 1) * 64 + zb_] = zr[m].y;
            zd[(kl + 2) * 64 + zb_] = zr[m].z;
            zd[(kl + 3) * 64 + zb_] = zr[m].w;
            wd[(kl + 0) * 64 + wr_] = dup2(wr[m].x);
            wd[(kl + 1) * 64 + wr_] = dup2(wr[m].y);
            wd[(kl + 2) * 64 + wr_] = dup2(wr[m].z);
            wd[(kl + 3) * 64 + wr_] = dup2(wr[m].w);
        }
    };

    const int ig = tid & 15, jg = tid >> 4;
    ull a00=0,a01=0,a10=0,a11=0,a20=0,a21=0,a30=0,a31=0;

    stage_load(0); stage_store(0); __syncthreads();
    for (int c = 0; c < 4; c++) {
        const int buf = c & 1;
        if (c + 1 < 4) stage_load(c + 1);
        const float* zbp = zs + buf * 4096;
        const ull*   wbp = ws + buf * 4096;
        #pragma unroll 8
        for (int k = 0; k < 64; k++) {
            ulonglong2 zz  = *(const ulonglong2*)&zbp[k * 64 + ig * 4];
            ulonglong2 w01 = *(const ulonglong2*)&wbp[k * 64 + jg * 4];
            ulonglong2 w23 = *(const ulonglong2*)&wbp[k * 64 + jg * 4 + 2];
            fma2(a00, w01.x, zz.x); fma2(a01, w01.x, zz.y);
            fma2(a10, w01.y, zz.x); fma2(a11, w01.y, zz.y);
            fma2(a20, w23.x, zz.x); fma2(a21, w23.x, zz.y);
            fma2(a30, w23.y, zz.x); fma2(a31, w23.y, zz.y);
        }
        __syncthreads();
        if (c + 1 < 4) { stage_store(buf ^ 1); __syncthreads(); }
    }

    int r0 = rowbase + jg * 4;
    float2 u00=unp(a00),u01=unp(a01),u10=unp(a10),u11=unp(a11);
    float2 u20=unp(a20),u21=unp(a21),u30=unp(a30),u31=unp(a31);
    float vx[4][4] = {{u00.x,u10.x,u20.x,u30.x},{u00.y,u10.y,u20.y,u30.y},
                      {u01.x,u11.x,u21.x,u31.x},{u01.y,u11.y,u21.y,u31.y}};
    #pragma unroll
    for (int j = 0; j < 4; j++) {
        float bs = bih[r0 + j] + bhh[r0 + j];
        float4 v = make_float4(vx[0][j]+bs, vx[1][j]+bs, vx[2][j]+bs, vx[3][j]+bs);
        *(float4*)(g_GX + ((size_t)t * G4 + r0 + j) * B_ + ig * 4) = v;
    }
}

// ---------------------------------------------------------------------------
// grid barrier (per btile group of 64 CTAs)
// ---------------------------------------------------------------------------
__device__ __forceinline__ void gsync(int grp)
{
    __threadfence();
    __syncthreads();
    if (threadIdx.x == 0) {
        unsigned g = g_gen2[grp];
        if (atomicAdd(&g_cnt2[grp], 1) == NGRP - 1) {
            g_cnt2[grp] = 0;
            __threadfence();
            g_gen2[grp] = g + 1;
        } else {
            while (g_gen2[grp] == g) { }
            __threadfence();
        }
    }
    __syncthreads();
}

// ---------------------------------------------------------------------------
// Persistent recurrent kernel. 128 CTAs = 64 htiles x 2 btiles. 1 CTA/SM.
// CTA owns 8 h-values x 32 batches: 32 gate rows. W slice (32 rows x 512 k,
// f32x2-dup, 128KB) resident in smem. z = hT[t] read DIRECTLY from L1/L2 by
// the GEMM inner loop (no staging). Thread: (ks 0..3, jg 0..7, ig 0..7):
// 4 rows x 4 batches x 128 k. K-split partials reduced via psm, fused ew.
// ---------------------------------------------------------------------------
__global__ __launch_bounds__(256, 1) void recurrent_kernel(
    const float* __restrict__ ic,
    const float* __restrict__ whh,
    float* __restrict__ out_h,
    float* __restrict__ out_c)
{
    extern __shared__ __align__(16) char smraw[];
    ull*   wsm  = (ull*)smraw;                       // [512][32] dup'd  128KB
    float* psm  = (float*)(smraw + 512 * 32 * 8);    // [4ks][32r][32b]   16KB
    float* trsm = psm + 4 * 32 * 32;                 // [5ch][32b][9]    5.8KB

    const int tid = threadIdx.x;
    const int ht  = blockIdx.x >> 1;
    const int bt  = blockIdx.x & 1;

    // ---- stage W once: wsm[k][r] = dup2(whh[grow(r)][k]) ----
    {
        const int kq = tid >> 5, r = tid & 31;        // 8 k-chunks x 32 rows
        const int grow = (r >> 3) * H_ + ht * HT + (r & 7);
        const float* wrow = whh + (size_t)grow * H_ + kq * 64;
        #pragma unroll
        for (int j = 0; j < 64; j += 4) {
            float4 v = *(const float4*)(wrow + j);
            int k = kq * 64 + j;
            wsm[(size_t)(k + 0) * 32 + r] = dup2(v.x);
            wsm[(size_t)(k + 1) * 32 + r] = dup2(v.y);
            wsm[(size_t)(k + 2) * 32 + r] = dup2(v.z);
            wsm[(size_t)(k + 3) * 32 + r] = dup2(v.w);
        }
    }

    // ---- per-thread maps ----
    const int ks = tid >> 6;            // k-slice (0..3)
    const int jg = (tid >> 3) & 7;      // row group (4 rows)
    const int ig = tid & 7;             // batch group (4 batches)
    const int hl = tid >> 5;            // ew: h-local (0..7)
    const int bl = tid & 31;            // ew: batch-local (0..31)
    const int h  = ht * HT + hl;
    const int b  = bt * BT + bl;
    float creg = ic[(size_t)b * H_ + h];

    __syncthreads();

    for (int t = 0; t < T_; t++) {
        // prefetch GX operands (independent of the barrier)
        const size_t gxb = (size_t)t * G4 * B_ + (size_t)h * B_ + b;
        float gx0 = g_GX[gxb];
        float gx1 = g_GX[gxb + (size_t)H_ * B_];
        float gx2 = g_GX[gxb + (size_t)2 * H_ * B_];
        float gx3 = g_GX[gxb + (size_t)3 * H_ * B_];

        if (t > 0) gsync(bt);           // hT(t) visible group-wide

        // ---- GEMM: rows jg*4..+3, batches ig*4..+3, k in [ks*128, +128) ----
        ull a00=0,a01=0,a10=0,a11=0,a20=0,a21=0,a30=0,a31=0;
        {
            const ull*   wp = wsm + (size_t)(ks * 128) * 32 + jg * 4;
            const float* zp = g_hT + (size_t)t * H_ * B_
                            + (size_t)(ks * 128) * B_ + bt * BT + ig * 4;
            #pragma unroll 8
            for (int kl = 0; kl < 128; kl++) {
                ulonglong2 w01 = *(const ulonglong2*)(wp + (size_t)kl * 32);
                ulonglong2 w23 = *(const ulonglong2*)(wp + (size_t)kl * 32 + 2);
                ulonglong2 zz  = *(const ulonglong2*)(zp + (size_t)kl * B_);
                fma2(a00, w01.x, zz.x); fma2(a01, w01.x, zz.y);
                fma2(a10, w01.y, zz.x); fma2(a11, w01.y, zz.y);
                fma2(a20, w23.x, zz.x); fma2(a21, w23.x, zz.y);
                fma2(a30, w23.y, zz.x); fma2(a31, w23.y, zz.y);
            }
        }

        // ---- write partials psm[ks][r][32b] ----
        {
            float2 p0, p1;
            p0 = unp(a00); p1 = unp(a01);
            *(float4*)&psm[((ks * 32) + jg * 4 + 0) * 32 + ig * 4] = make_float4(p0.x,p0.y,p1.x,p1.y);
            p0 = unp(a10); p1 = unp(a11);
            *(float4*)&psm[((ks * 32) + jg * 4 + 1) * 32 + ig * 4] = make_float4(p0.x,p0.y,p1.x,p1.y);
            p0 = unp(a20); p1 = unp(a21);
            *(float4*)&psm[((ks * 32) + jg * 4 + 2) * 32 + ig * 4] = make_float4(p0.x,p0.y,p1.x,p1.y);
            p0 = unp(a30); p1 = unp(a31);
            *(float4*)&psm[((ks * 32) + jg * 4 + 3) * 32 + ig * 4] = make_float4(p0.x,p0.y,p1.x,p1.y);
        }
        __syncthreads();

        // ---- fused elementwise for (h, b) ----
        {
            float gi = gx0, gf = gx1, gg = gx2, go = gx3;
            #pragma unroll
            for (int s = 0; s < 4; s++) {
                gi += psm[(s * 32 + 0 * 8 + hl) * 32 + bl];
                gf += psm[(s * 32 + 1 * 8 + hl) * 32 + bl];
                gg += psm[(s * 32 + 2 * 8 + hl) * 32 + bl];
                go += psm[(s * 32 + 3 * 8 + hl) * 32 + bl];
            }

            float i_ = sigf(gi);
            float f_ = sigf(gf);
            float g_ = tanhfast(gg);
            float o_ = sigf(go);

            float cy = f_ * creg + i_ * g_;
            float hy = o_ * tanhfast(cy);

            trsm[(0 * 32 + bl) * 9 + hl] = g_ * i_ * (1.f - i_);
            trsm[(1 * 32 + bl) * 9 + hl] = creg * f_ * (1.f - f_);
            trsm[(2 * 32 + bl) * 9 + hl] = i_ * (1.f - g_ * g_);
            trsm[(3 * 32 + bl) * 9 + hl] = f_;
            trsm[(4 * 32 + bl) * 9 + hl] = hy;
            creg = cy;

            __stcg(g_hT + ((size_t)(t + 1) * H_ + h) * B_ + b, hy);
        }
        __syncthreads();

        // ---- coalesced float4 writes of transposed per-CTA outputs ----
        #pragma unroll
        for (int task = tid; task < 320; task += 256) {
            int ch = task >> 6, rem = task & 63, bb = rem >> 1, h4 = rem & 1;
            const float* tp = &trsm[(ch * 32 + bb) * 9 + h4 * 4];
            float4 v = make_float4(tp[0], tp[1], tp[2], tp[3]);
            int gb = bt * BT + bb;
            if (ch < 4)
                *(float4*)(g_D4 + ((size_t)t * B_ + gb) * 2048 + ch * H_ + ht * HT + h4 * 4) = v;
            else
                *(float4*)(out_h + ((size_t)t * B_ + gb) * H_ + ht * HT + h4 * 4) = v;
        }
        __syncthreads();
    }

    out_c[(size_t)b * H_ + h] = creg;
}

// ---------------------------------------------------------------------------
// scan: suffix product of f scales d channels in place; accumulates ev_b.
// ---------------------------------------------------------------------------
__global__ __launch_bounds__(256) void scan_kernel(float* __restrict__ out_evb)
{
    const int u = blockIdx.x * 256 + threadIdx.x;
    const int b = u >> 9, h = u & (H_ - 1);
    float coef = 1.f, si = 0.f, sf = 0.f, sg = 0.f;
    for (int t = T_ - 1; t >= 0; t--) {
        size_t base = ((size_t)t * B_ + b) * 2048;
        float f  = g_D4[base + 3 * H_ + h];
        float di = g_D4[base + h]          * coef;
        float df = g_D4[base + H_ + h]     * coef;
        float dg = g_D4[base + 2 * H_ + h] * coef;
        g_D4[base + h]          = di;
        g_D4[base + H_ + h]     = df;
        g_D4[base + 2 * H_ + h] = dg;
        si += di; sf += df; sg += dg;
        coef *= f;
    }
    out_evb[b * TH + h]          = si;
    out_evb[b * TH + H_ + h]     = sf;
    out_evb[b * TH + 2 * H_ + h] = sg;
}

// ---------------------------------------------------------------------------
// phase 3: C[b] = D_b^T (3H x T) @ Z_b (T x N), f32x2.
// ---------------------------------------------------------------------------
__global__ __launch_bounds__(256) void outer_kernel(
    const float* __restrict__ src, const float* __restrict__ init_h,
    const float* __restrict__ out_h, float* __restrict__ outC, int N, int mode)
{
    extern __shared__ __align__(16) char smraw[];
    ull*   Dsm = (ull*)smraw;                            // [T_][64] dup'd
    float* Xsm = (float*)(smraw + (size_t)T_ * 64 * 8);  // [T_][64]

    const int tid = threadIdx.x;
    const int ibase = blockIdx.x * 64, jbase = blockIdx.y * 64, b = blockIdx.z;

    for (int idx = tid; idx < T_ * 16; idx += 256) {
        int t = idx >> 4, j4 = (idx & 15) * 4;
        float4 v = *(const float4*)(g_D4 + ((size_t)t * B_ + b) * 2048 + jbase + j4);
        Dsm[t * 64 + j4 + 0] = dup2(v.x);
        Dsm[t * 64 + j4 + 1] = dup2(v.y);
        Dsm[t * 64 + j4 + 2] = dup2(v.z);
        Dsm[t * 64 + j4 + 3] = dup2(v.w);
    }
    for (int idx = tid; idx < T_ * 16; idx += 256) {
        int t = idx >> 4, i4 = (idx & 15) * 4;
        const float* p;
        if (mode == 0) p = src + ((size_t)t * B_ + b) * I_ + ibase + i4;
        else p = (t == 0) ? (init_h + (size_t)b * H_ + ibase + i4)
                          : (out_h + ((size_t)(t - 1) * B_ + b) * H_ + ibase + i4);
        *(float4*)&Xsm[t * 64 + i4] = *(const float4*)p;
    }
    __syncthreads();

    const int jg = tid >> 4, ig = tid & 15;
    ull a00=0,a01=0,a10=0,a11=0,a20=0,a21=0,a30=0,a31=0;

    #pragma unroll 4
    for (int t = 0; t < T_; t++) {
        ulonglong2 d01 = *(const ulonglong2*)&Dsm[t * 64 + jg * 4];
        ulonglong2 d23 = *(const ulonglong2*)&Dsm[t * 64 + jg * 4 + 2];
        ulonglong2 xx  = *(const ulonglong2*)&Xsm[t * 64 + ig * 4];
        fma2(a00, d01.x, xx.x); fma2(a01, d01.x, xx.y);
        fma2(a10, d01.y, xx.x); fma2(a11, d01.y, xx.y);
        fma2(a20, d23.x, xx.x); fma2(a21, d23.x, xx.y);
        fma2(a30, d23.y, xx.x); fma2(a31, d23.y, xx.y);
    }

    size_t obase = (size_t)b * TH * N + ibase + ig * 4;
    const int j0 = jbase + jg * 4;
    float2 u; float4 v;
    u = unp(a00); v.x = u.x; v.y = u.y; u = unp(a01); v.z = u.x; v.w = u.y;
    *(float4*)(outC + obase + (size_t)(j0 + 0) * N) = v;
    u = unp(a10); v.x = u.x; v.y = u.y; u = unp(a11); v.z = u.x; v.w = u.y;
    *(float4*)(outC + obase + (size_t)(j0 + 1) * N) = v;
    u = unp(a20); v.x = u.x; v.y = u.y; u = unp(a21); v.z = u.x; v.w = u.y;
    *(float4*)(outC + obase + (size_t)(j0 + 2) * N) = v;
    u = unp(a30); v.x = u.x; v.y = u.y; u = unp(a31); v.z = u.x; v.w = u.y;
    *(float4*)(outC + obase + (size_t)(j0 + 3) * N) = v;
}

// ---------------------------------------------------------------------------

extern "C" void kernel_launch(void* const* d_in, const int* in_sizes, int n_in,
                              void* d_out, int out_size)
{
    const float* input = (const float*)d_in[0];
    const float* ih    = (const float*)d_in[1];
    const float* ic    = (const float*)d_in[2];
    const float* wih   = (const float*)d_in[3];
    const float* whh   = (const float*)d_in[4];
    const float* bih   = (const float*)d_in[5];
    const float* bhh   = (const float*)d_in[6];

    float* out      = (float*)d_out;
    float* out_h    = out;                                // [T,B,H]
    float* out_c    = out_h  + (size_t)T_ * B_ * H_;      // [B,H]
    float* out_evih = out_c  + (size_t)B_ * H_;           // [B,3H,I]
    float* out_evhh = out_evih + (size_t)B_ * TH * I_;    // [B,3H,H]
    float* out_evb  = out_evhh + (size_t)B_ * TH * H_;    // [B,3H,1]

    const int smem_gemm  = 2 * 64 * 64 * 4 + 2 * 64 * 64 * 8;        // 96KB
    const int smem_rec   = 512 * 32 * 8 + 4 * 32 * 32 * 4
                         + 5 * 32 * 9 * 4;                            // ~153KB
    const int smem_outer = T_ * 64 * 8 + T_ * 64 * 4;                 // 75KB

    cudaFuncSetAttribute(gx_kernel, cudaFuncAttributeMaxDynamicSharedMemorySize, smem_gemm);
    cudaFuncSetAttribute(recurrent_kernel, cudaFuncAttributeMaxDynamicSharedMemorySize, smem_rec);
    cudaFuncSetAttribute(outer_kernel, cudaFuncAttributeMaxDynamicSharedMemorySize, smem_outer);

    init_hT_kernel<<<128, 256>>>(ih);
    gx_kernel<<<dim3(32, T_), 256, smem_gemm>>>(input, wih, bih, bhh);

    recurrent_kernel<<<128, 256, smem_rec>>>(ic, whh, out_h, out_c);

    scan_kernel<<<128, 256>>>(out_evb);

    outer_kernel<<<dim3(I_ / 64, TH / 64, B_), 256, smem_outer>>>(
        input, ih, out_h, out_evih, I_, 0);
    outer_kernel<<<dim3(H_ / 64, TH / 64, B_), 256, smem_outer>>>(
        input, ih, out_h, out_evhh, H_, 1);
}

// round 11
// speedup vs baseline: 1.3837x; 1.0363x over previous
#include <cuda_runtime.h>
#include <math.h>

#define T_  100
#define B_  64
#define I_  256
#define H_  512
#define G4  2048            // 4*H
#define TH  1536            // 3*H
#define HT  8               // h per CTA
#define BT  32              // batches per CTA
#define NGRP 64             // CTAs per barrier group

typedef unsigned long long ull;

// ------------------------- scratch (device globals) -------------------------
__device__ float g_GX[(size_t)T_ * G4 * B_];          // x@Wih^T + biases  [t][row][b]
__device__ float g_hT[(size_t)(T_ + 1) * H_ * B_];    // h transposed      [slot][k][b]
__device__ float g_D4[(size_t)T_ * B_ * 2048];        // [t][b][{di,df,dg,f}*512]

// grid barrier state (one per btile group)
__device__ unsigned g_cnt2[2] = {0, 0};
__device__ volatile unsigned g_gen2[2] = {0, 0};

// ------------------------- f32x2 helpers -----------------------------------
__device__ __forceinline__ ull dup2(float x) {
    ull r; asm("mov.b64 %0, {%1, %1};" : "=l"(r) : "f"(x)); return r;
}
__device__ __forceinline__ void fma2(ull& a, ull x, ull y) {
    asm("fma.rn.f32x2 %0, %1, %2, %0;" : "+l"(a) : "l"(x), "l"(y));
}
__device__ __forceinline__ float2 unp(ull v) {
    float2 r; asm("mov.b64 {%0, %1}, %2;" : "=f"(r.x), "=f"(r.y) : "l"(v)); return r;
}
__device__ __forceinline__ float sigf(float x) { return 1.0f / (1.0f + __expf(-x)); }
__device__ __forceinline__ float tanhfast(float x) {
    float e = __expf(-2.0f * fabsf(x));
    float r = (1.0f - e) / (1.0f + e);
    return copysignf(r, x);
}

// ------------------------- init: transpose initial_h ------------------------
__global__ __launch_bounds__(256) void init_hT_kernel(const float* __restrict__ ih)
{
    int u = blockIdx.x * 256 + threadIdx.x;      // 32768 threads
    int h = u >> 6, b = u & 63;
    g_hT[(size_t)h * B_ + b] = ih[b * H_ + h];
}

// ---------------------------------------------------------------------------
// GX kernel: GX[t][row][b] = sum_k x[t][b][k]*Wih[row][k] + bih[row]+bhh[row]
// ---------------------------------------------------------------------------
__global__ __launch_bounds__(256) void gx_kernel(
    const float* __restrict__ x, const float* __restrict__ wih,
    const float* __restrict__ bih, const float* __restrict__ bhh)
{
    extern __shared__ __align__(16) char smraw[];
    float* zs = (float*)smraw;                    // [2][64][64] floats (32KB)
    ull*   ws = (ull*)(smraw + 2 * 64 * 64 * 4);  // [2][64][64] ull   (64KB)

    const int tid = threadIdx.x;
    const int rowbase = blockIdx.x * 64;
    const int t = blockIdx.y;
    const float* xt = x + (size_t)t * B_ * I_;

    const int zb_ = tid & 63, zq = tid >> 6;
    const int wr_ = tid & 63, wq = tid >> 6;

    float4 zr[4], wr[4];
    auto stage_load = [&](int c) {
        const int kc0 = c * 64;
        #pragma unroll
        for (int m = 0; m < 4; m++) {
            int kl = zq * 16 + m * 4;
            zr[m] = *(const float4*)(xt + (size_t)zb_ * I_ + kc0 + kl);
            wr[m] = *(const float4*)(wih + (size_t)(rowbase + wr_) * I_ + kc0 + kl);
        }
    };
    auto stage_store = [&](int buf) {
        float* zd = zs + buf * 4096;
        ull*   wd = ws + buf * 4096;
        #pragma unroll
        for (int m = 0; m < 4; m++) {
            int kl = zq * 16 + m * 4;
            zd[(kl + 0) * 64 + zb_] = zr[m].x;
            zd[(kl + 1) * 64 + zb_] = zr[m].y;
            zd[(kl + 2) * 64 + zb_] = zr[m].z;
            zd[(kl + 3) * 64 + zb_] = zr[m].w;
            wd[(kl + 0) * 64 + wr_] = dup2(wr[m].x);
            wd[(kl + 1) * 64 + wr_] = dup2(wr[m].y);
            wd[(kl + 2) * 64 + wr_] = dup2(wr[m].z);
            wd[(kl + 3) * 64 + wr_] = dup2(wr[m].w);
        }
    };

    const int ig = tid & 15, jg = tid >> 4;
    ull a00=0,a01=0,a10=0,a11=0,a20=0,a21=0,a30=0,a31=0;

    stage_load(0); stage_store(0); __syncthreads();
    for (int c = 0; c < 4; c++) {
        const int buf = c & 1;
        if (c + 1 < 4) stage_load(c + 1);
        const float* zbp = zs + buf * 4096;
        const ull*   wbp = ws + buf * 4096;
        #pragma unroll 8
        for (int k = 0; k < 64; k++) {
            ulonglong2 zz  = *(const ulonglong2*)&zbp[k * 64 + ig * 4];
            ulonglong2 w01 = *(const ulonglong2*)&wbp[k * 64 + jg * 4];
            ulonglong2 w23 = *(const ulonglong2*)&wbp[k * 64 + jg * 4 + 2];
            fma2(a00, w01.x, zz.x); fma2(a01, w01.x, zz.y);
            fma2(a10, w01.y, zz.x); fma2(a11, w01.y, zz.y);
            fma2(a20, w23.x, zz.x); fma2(a21, w23.x, zz.y);
            fma2(a30, w23.y, zz.x); fma2(a31, w23.y, zz.y);
        }
        __syncthreads();
        if (c + 1 < 4) { stage_store(buf ^ 1); __syncthreads(); }
    }

    int r0 = rowbase + jg * 4;
    float2 u00=unp(a00),u01=unp(a01),u10=unp(a10),u11=unp(a11);
    float2 u20=unp(a20),u21=unp(a21),u30=unp(a30),u31=unp(a31);
    float vx[4][4] = {{u00.x,u10.x,u20.x,u30.x},{u00.y,u10.y,u20.y,u30.y},
                      {u01.x,u11.x,u21.x,u31.x},{u01.y,u11.y,u21.y,u31.y}};
    #pragma unroll
    for (int j = 0; j < 4; j++) {
        float bs = bih[r0 + j] + bhh[r0 + j];
        float4 v = make_float4(vx[0][j]+bs, vx[1][j]+bs, vx[2][j]+bs, vx[3][j]+bs);
        *(float4*)(g_GX + ((size_t)t * G4 + r0 + j) * B_ + ig * 4) = v;
    }
}

// ---------------------------------------------------------------------------
// Persistent recurrent kernel. 128 CTAs = 64 htiles x 2 btiles. 1 CTA/SM.
// Split arrive/wait barrier: after stcg of h(t+1) the CTA arrives; the D4 /
// out_h epilogue stores run between arrive and wait (hidden behind skew).
// Replay-safe generation targets: gbase snapshotted at kernel start.
// ---------------------------------------------------------------------------
__global__ __launch_bounds__(256, 1) void recurrent_kernel(
    const float* __restrict__ ic,
    const float* __restrict__ whh,
    float* __restrict__ out_h,
    float* __restrict__ out_c)
{
    extern __shared__ __align__(16) char smraw[];
    ull*   wsm  = (ull*)smraw;                       // [512][32] dup'd  128KB
    float* psm  = (float*)(smraw + 512 * 32 * 8);    // [4ks][32r][32b]   16KB
    float* trsm = psm + 4 * 32 * 32;                 // [5ch][32b][9]    5.8KB

    const int tid = threadIdx.x;
    const int ht  = blockIdx.x >> 1;
    const int bt  = blockIdx.x & 1;

    // snapshot barrier generation base BEFORE any CTA can complete step 0
    unsigned gbase = 0;
    if (tid == 0) gbase = g_gen2[bt];

    // ---- stage W once: wsm[k][r] = dup2(whh[grow(r)][k]) ----
    {
        const int kq = tid >> 5, r = tid & 31;        // 8 k-chunks x 32 rows
        const int grow = (r >> 3) * H_ + ht * HT + (r & 7);
        const float* wrow = whh + (size_t)grow * H_ + kq * 64;
        #pragma unroll
        for (int j = 0; j < 64; j += 4) {
            float4 v = *(const float4*)(wrow + j);
            int k = kq * 64 + j;
            wsm[(size_t)(k + 0) * 32 + r] = dup2(v.x);
            wsm[(size_t)(k + 1) * 32 + r] = dup2(v.y);
            wsm[(size_t)(k + 2) * 32 + r] = dup2(v.z);
            wsm[(size_t)(k + 3) * 32 + r] = dup2(v.w);
        }
    }

    // ---- per-thread maps ----
    const int ks = tid >> 6;            // k-slice (0..3)
    const int jg = (tid >> 3) & 7;      // row group (4 rows)
    const int ig = tid & 7;             // batch group (4 batches)
    const int hl = tid >> 5;            // ew: h-local (0..7)
    const int bl = tid & 31;            // ew: batch-local (0..31)
    const int h  = ht * HT + hl;
    const int b  = bt * BT + bl;
    float creg = ic[(size_t)b * H_ + h];

    __syncthreads();

    for (int t = 0; t < T_; t++) {
        // prefetch GX operands (overlaps the wait below)
        const size_t gxb = (size_t)t * G4 * B_ + (size_t)h * B_ + b;
        float gx0 = g_GX[gxb];
        float gx1 = g_GX[gxb + (size_t)H_ * B_];
        float gx2 = g_GX[gxb + (size_t)2 * H_ * B_];
        float gx3 = g_GX[gxb + (size_t)3 * H_ * B_];

        // ---- WAIT: hT(t) must be published (t=0: init kernel did it) ----
        if (t > 0) {
            if (tid == 0) {
                unsigned target = gbase + (unsigned)t;
                while (g_gen2[bt] != target) { }
            }
            __syncthreads();
        }

        // ---- GEMM: rows jg*4..+3, batches ig*4..+3, k in [ks*128, +128) ----
        ull a00=0,a01=0,a10=0,a11=0,a20=0,a21=0,a30=0,a31=0;
        {
            const ull*   wp = wsm + (size_t)(ks * 128) * 32 + jg * 4;
            const float* zp = g_hT + (size_t)t * H_ * B_
                            + (size_t)(ks * 128) * B_ + bt * BT + ig * 4;
            #pragma unroll 8
            for (int kl = 0; kl < 128; kl++) {
                ulonglong2 w01 = *(const ulonglong2*)(wp + (size_t)kl * 32);
                ulonglong2 w23 = *(const ulonglong2*)(wp + (size_t)kl * 32 + 2);
                ulonglong2 zz  = *(const ulonglong2*)(zp + (size_t)kl * B_);
                fma2(a00, w01.x, zz.x); fma2(a01, w01.x, zz.y);
                fma2(a10, w01.y, zz.x); fma2(a11, w01.y, zz.y);
                fma2(a20, w23.x, zz.x); fma2(a21, w23.x, zz.y);
                fma2(a30, w23.y, zz.x); fma2(a31, w23.y, zz.y);
            }
        }

        // ---- write partials psm[ks][r][32b] ----
        {
            float2 p0, p1;
            p0 = unp(a00); p1 = unp(a01);
            *(float4*)&psm[((ks * 32) + jg * 4 + 0) * 32 + ig * 4] = make_float4(p0.x,p0.y,p1.x,p1.y);
            p0 = unp(a10); p1 = unp(a11);
            *(float4*)&psm[((ks * 32) + jg * 4 + 1) * 32 + ig * 4] = make_float4(p0.x,p0.y,p1.x,p1.y);
            p0 = unp(a20); p1 = unp(a21);
            *(float4*)&psm[((ks * 32) + jg * 4 + 2) * 32 + ig * 4] = make_float4(p0.x,p0.y,p1.x,p1.y);
            p0 = unp(a30); p1 = unp(a31);
            *(float4*)&psm[((ks * 32) + jg * 4 + 3) * 32 + ig * 4] = make_float4(p0.x,p0.y,p1.x,p1.y);
        }
        __syncthreads();

        // ---- fused elementwise for (h, b): critical part first ----
        {
            float gi = gx0, gf = gx1, gg = gx2, go = gx3;
            #pragma unroll
            for (int s = 0; s < 4; s++) {
                gi += psm[(s * 32 + 0 * 8 + hl) * 32 + bl];
                gf += psm[(s * 32 + 1 * 8 + hl) * 32 + bl];
                gg += psm[(s * 32 + 2 * 8 + hl) * 32 + bl];
                go += psm[(s * 32 + 3 * 8 + hl) * 32 + bl];
            }

            float i_ = sigf(gi);
            float f_ = sigf(gf);
            float g_ = tanhfast(gg);
            float o_ = sigf(go);

            float cy = f_ * creg + i_ * g_;
            float hy = o_ * tanhfast(cy);

            // publish h(t+1) ASAP — this is the only cross-CTA dependency
            __stcg(g_hT + ((size_t)(t + 1) * H_ + h) * B_ + b, hy);

            // off-critical-path d-terms into the transpose buffer
            trsm[(0 * 32 + bl) * 9 + hl] = g_ * i_ * (1.f - i_);
            trsm[(1 * 32 + bl) * 9 + hl] = creg * f_ * (1.f - f_);
            trsm[(2 * 32 + bl) * 9 + hl] = i_ * (1.f - g_ * g_);
            trsm[(3 * 32 + bl) * 9 + hl] = f_;
            trsm[(4 * 32 + bl) * 9 + hl] = hy;
            creg = cy;
        }

        // ---- ARRIVE: make hT(t+1) visible, signal the group ----
        __threadfence();
        __syncthreads();          // also orders trsm writes for the epilogue
        if (tid == 0) {
            if (atomicAdd(&g_cnt2[bt], 1) == NGRP - 1) {
                g_cnt2[bt] = 0;
                __threadfence();
                g_gen2[bt] = gbase + (unsigned)(t + 1);
            }
        }

        // ---- epilogue in the barrier's shadow: D4 / out_h stores ----
        #pragma unroll
        for (int task = tid; task < 320; task += 256) {
            int ch = task >> 6, rem = task & 63, bb = rem >> 1, h4 = rem & 1;
            const float* tp = &trsm[(ch * 32 + bb) * 9 + h4 * 4];
            float4 v = make_float4(tp[0], tp[1], tp[2], tp[3]);
            int gb = bt * BT + bb;
            if (ch < 4)
                *(float4*)(g_D4 + ((size_t)t * B_ + gb) * 2048 + ch * H_ + ht * HT + h4 * 4) = v;
            else
                *(float4*)(out_h + ((size_t)t * B_ + gb) * H_ + ht * HT + h4 * 4) = v;
        }
        // no sync: next iteration's wait orders everything
    }

    out_c[(size_t)b * H_ + h] = creg;
}

// ---------------------------------------------------------------------------
// scan: suffix product of f scales d channels in place; accumulates ev_b.
// ---------------------------------------------------------------------------
__global__ __launch_bounds__(256) void scan_kernel(float* __restrict__ out_evb)
{
    const int u = blockIdx.x * 256 + threadIdx.x;
    const int b = u >> 9, h = u & (H_ - 1);
    float coef = 1.f, si = 0.f, sf = 0.f, sg = 0.f;
    for (int t = T_ - 1; t >= 0; t--) {
        size_t base = ((size_t)t * B_ + b) * 2048;
        float f  = g_D4[base + 3 * H_ + h];
        float di = g_D4[base + h]          * coef;
        float df = g_D4[base + H_ + h]     * coef;
        float dg = g_D4[base + 2 * H_ + h] * coef;
        g_D4[base + h]          = di;
        g_D4[base + H_ + h]     = df;
        g_D4[base + 2 * H_ + h] = dg;
        si += di; sf += df; sg += dg;
        coef *= f;
    }
    out_evb[b * TH + h]          = si;
    out_evb[b * TH + H_ + h]     = sf;
    out_evb[b * TH + 2 * H_ + h] = sg;
}

// ---------------------------------------------------------------------------
// phase 3: C[b] = D_b^T (3H x T) @ Z_b (T x N), f32x2.
// ---------------------------------------------------------------------------
__global__ __launch_bounds__(256) void outer_kernel(
    const float* __restrict__ src, const float* __restrict__ init_h,
    const float* __restrict__ out_h, float* __restrict__ outC, int N, int mode)
{
    extern __shared__ __align__(16) char smraw[];
    ull*   Dsm = (ull*)smraw;                            // [T_][64] dup'd
    float* Xsm = (float*)(smraw + (size_t)T_ * 64 * 8);  // [T_][64]

    const int tid = threadIdx.x;
    const int ibase = blockIdx.x * 64, jbase = blockIdx.y * 64, b = blockIdx.z;

    for (int idx = tid; idx < T_ * 16; idx += 256) {
        int t = idx >> 4, j4 = (idx & 15) * 4;
        float4 v = *(const float4*)(g_D4 + ((size_t)t * B_ + b) * 2048 + jbase + j4);
        Dsm[t * 64 + j4 + 0] = dup2(v.x);
        Dsm[t * 64 + j4 + 1] = dup2(v.y);
        Dsm[t * 64 + j4 + 2] = dup2(v.z);
        Dsm[t * 64 + j4 + 3] = dup2(v.w);
    }
    for (int idx = tid; idx < T_ * 16; idx += 256) {
        int t = idx >> 4, i4 = (idx & 15) * 4;
        const float* p;
        if (mode == 0) p = src + ((size_t)t * B_ + b) * I_ + ibase + i4;
        else p = (t == 0) ? (init_h + (size_t)b * H_ + ibase + i4)
                          : (out_h + ((size_t)(t - 1) * B_ + b) * H_ + ibase + i4);
        *(float4*)&Xsm[t * 64 + i4] = *(const float4*)p;
    }
    __syncthreads();

    const int jg = tid >> 4, ig = tid & 15;
    ull a00=0,a01=0,a10=0,a11=0,a20=0,a21=0,a30=0,a31=0;

    #pragma unroll 4
    for (int t = 0; t < T_; t++) {
        ulonglong2 d01 = *(const ulonglong2*)&Dsm[t * 64 + jg * 4];
        ulonglong2 d23 = *(const ulonglong2*)&Dsm[t * 64 + jg * 4 + 2];
        ulonglong2 xx  = *(const ulonglong2*)&Xsm[t * 64 + ig * 4];
        fma2(a00, d01.x, xx.x); fma2(a01, d01.x, xx.y);
        fma2(a10, d01.y, xx.x); fma2(a11, d01.y, xx.y);
        fma2(a20, d23.x, xx.x); fma2(a21, d23.x, xx.y);
        fma2(a30, d23.y, xx.x); fma2(a31, d23.y, xx.y);
    }

    size_t obase = (size_t)b * TH * N + ibase + ig * 4;
    const int j0 = jbase + jg * 4;
    float2 u; float4 v;
    u = unp(a00); v.x = u.x; v.y = u.y; u = unp(a01); v.z = u.x; v.w = u.y;
    *(float4*)(outC + obase + (size_t)(j0 + 0) * N) = v;
    u = unp(a10); v.x = u.x; v.y = u.y; u = unp(a11); v.z = u.x; v.w = u.y;
    *(float4*)(outC + obase + (size_t)(j0 + 1) * N) = v;
    u = unp(a20); v.x = u.x; v.y = u.y; u = unp(a21); v.z = u.x; v.w = u.y;
    *(float4*)(outC + obase + (size_t)(j0 + 2) * N) = v;
    u = unp(a30); v.x = u.x; v.y = u.y; u = unp(a31); v.z = u.x; v.w = u.y;
    *(float4*)(outC + obase + (size_t)(j0 + 3) * N) = v;
}

// ---------------------------------------------------------------------------

extern "C" void kernel_launch(void* const* d_in, const int* in_sizes, int n_in,
                              void* d_out, int out_size)
{
    const float* input = (const float*)d_in[0];
    const float* ih    = (const float*)d_in[1];
    const float* ic    = (const float*)d_in[2];
    const float* wih   = (const float*)d_in[3];
    const float* whh   = (const float*)d_in[4];
    const float* bih   = (const float*)d_in[5];
    const float* bhh   = (const float*)d_in[6];

    float* out      = (float*)d_out;
    float* out_h    = out;                                // [T,B,H]
    float* out_c    = out_h  + (size_t)T_ * B_ * H_;      // [B,H]
    float* out_evih = out_c  + (size_t)B_ * H_;           // [B,3H,I]
    float* out_evhh = out_evih + (size_t)B_ * TH * I_;    // [B,3H,H]
    float* out_evb  = out_evhh + (size_t)B_ * TH * H_;    // [B,3H,1]

    const int smem_gemm  = 2 * 64 * 64 * 4 + 2 * 64 * 64 * 8;        // 96KB
    const int smem_rec   = 512 * 32 * 8 + 4 * 32 * 32 * 4
                         + 5 * 32 * 9 * 4;                            // ~153KB
    const int smem_outer = T_ * 64 * 8 + T_ * 64 * 4;                 // 75KB

    cudaFuncSetAttribute(gx_kernel, cudaFuncAttributeMaxDynamicSharedMemorySize, smem_gemm);
    cudaFuncSetAttribute(recurrent_kernel, cudaFuncAttributeMaxDynamicSharedMemorySize, smem_rec);
    cudaFuncSetAttribute(outer_kernel, cudaFuncAttributeMaxDynamicSharedMemorySize, smem_outer);

    init_hT_kernel<<<128, 256>>>(ih);
    gx_kernel<<<dim3(32, T_), 256, smem_gemm>>>(input, wih, bih, bhh);

    recurrent_kernel<<<128, 256, smem_rec>>>(ic, whh, out_h, out_c);

    scan_kernel<<<128, 256>>>(out_evb);

    outer_kernel<<<dim3(I_ / 64, TH / 64, B_), 256, smem_outer>>>(
        input, ih, out_h, out_evih, I_, 0);
    outer_kernel<<<dim3(H_ / 64, TH / 64, B_), 256, smem_outer>>>(
        input, ih, out_h, out_evhh, H_, 1);
}